// round 9
// baseline (speedup 1.0000x reference)
#include <cuda_runtime.h>
#include <cuda_fp16.h>

#define NX    512
#define NPTS  32768
#define CCH   64
#define NB    4
#define PLANE (NX * NX)
#define BVOL  (PLANE * CCH)
#define NTB   4096               // transpose blocks per batch
#define NGB   1024               // gather blocks per batch

// NHWC fp16 scratch (b, py, px, c). 134 MB; one batch slice = 33.5 MB.
__device__ __half    g_xt[(size_t)NB * BVOL];
__device__ unsigned  g_done[NB];          // T-completion counters

__device__ __forceinline__ unsigned ld_acquire(const unsigned* p) {
    unsigned v;
    asm volatile("ld.acquire.gpu.u32 %0, [%1];" : "=r"(v) : "l"(p));
    return v;
}

__global__ void init_kernel() {
    if (threadIdx.x < NB) g_done[threadIdx.x] = 0;
}

// ---------------------------------------------------------------------------
// Transpose role: 64 px x 64 ch tile of batch tb -> NHWC fp16 scratch.
// ---------------------------------------------------------------------------
__device__ __forceinline__ void do_transpose(char* smem, const float* __restrict__ x,
                                             int tb, int tile)
{
    float (*s)[65] = (float(*)[65])smem;      // [channel][pixel]
    const int p0   = tile * 64;
    const int slot = threadIdx.x & 15;        // float4 slot (4 px)
    const int c0   = threadIdx.x >> 4;        // 0..15

    const float* xb = x + (size_t)tb * BVOL;
    #pragma unroll
    for (int c = c0; c < 64; c += 16) {
        const float4 v = __ldcs((const float4*)(xb + (size_t)c * PLANE + p0 + slot * 4));
        s[c][slot * 4 + 0] = v.x;
        s[c][slot * 4 + 1] = v.y;
        s[c][slot * 4 + 2] = v.z;
        s[c][slot * 4 + 3] = v.w;
    }
    __syncthreads();

    __half* yb = g_xt + (size_t)tb * BVOL + (size_t)p0 * CCH;
    #pragma unroll
    for (int i = threadIdx.x; i < 64 * 32; i += 256) {
        const int p  = i >> 5;
        const int cp = i & 31;
        ((__half2*)(yb + (size_t)p * CCH))[cp] =
            __floats2half2_rn(s[2 * cp][p], s[2 * cp + 1][p]);
    }

    __syncthreads();                          // all stores issued
    if (threadIdx.x == 0) {
        __threadfence();                      // make scratch visible
        atomicAdd(&g_done[tb], 1u);
    }
}

// ---------------------------------------------------------------------------
// Gather role: 32 consecutive points of batch gb. Waits for T_gb first.
// ---------------------------------------------------------------------------
__device__ __forceinline__ void do_gather(char* smem, const float* __restrict__ coords,
                                          float* __restrict__ out, int gb, int gblk)
{
    float  (*s_w)[12]   = (float(*)[12])smem;              // 1536 B
    int    (*s_off)[12] = (int(*)[12])(smem + 1536);       // 1536 B
    float2 (*s_out)[33] = (float2(*)[33])(smem + 3072);    // 8448 B

    // Wait for all transpose blocks of batch gb (strictly earlier bids).
    if (threadIdx.x == 0) {
        while (ld_acquire(&g_done[gb]) < NTB) __nanosleep(128);
    }
    __syncthreads();

    const int n0  = gblk * 32;
    const int tid = threadIdx.x;

    if (tid < 32) {
        const int   n    = n0 + tid;
        const float cy   = coords[((size_t)gb * NPTS + n) * 2 + 0];
        const float cx   = coords[((size_t)gb * NPTS + n) * 2 + 1];
        const float posx = cx * 511.0f;
        const float posy = cy * 511.0f;
        const float rx   = rintf(posx);       // jnp.round = half-to-even
        const float ry   = rintf(posy);

        float wx[3] = {0.f, 0.f, 0.f};
        float wy[3] = {0.f, 0.f, 0.f};
        #pragma unroll
        for (int j = 0; j < 9; j++) {
            const float o  = 1.5f - 0.375f * (float)j;           // off_n[j]
            const float px = fminf(fmaxf(rx - o, 0.f), 512.f);   // clip hi = nx (ref quirk)
            const float py = fminf(fmaxf(ry - o, 0.f), 512.f);
            const float dx = px - posx;
            const float dy = py - posy;
            wx[j / 3] += __expf(-2.f * dx * dx);  // normal const cancels in norm
            wy[j / 3] += __expf(-2.f * dy * dy);
        }

        float w9[9];
        float s = 0.f;
        #pragma unroll
        for (int a = 0; a < 3; a++)
            #pragma unroll
            for (int c2 = 0; c2 < 3; c2++) {
                const float w = wx[a] * wy[c2];
                w9[a * 3 + c2] = w;
                s += w;
            }
        const float inv = 1.0f / s;

        const int irx = (int)rx;
        const int iry = (int)ry;
        int ixs[3], iys[3];
        #pragma unroll
        for (int a = 0; a < 3; a++) {
            ixs[a] = min(max(irx + 1 - a, 0), NX - 1);
            iys[a] = min(max(iry + 1 - a, 0), NX - 1);
        }

        #pragma unroll
        for (int a = 0; a < 3; a++)
            #pragma unroll
            for (int c2 = 0; c2 < 3; c2++) {
                s_w[tid][a * 3 + c2]   = w9[a * 3 + c2] * inv;
                s_off[tid][a * 3 + c2] = (ixs[a] * NX + iys[c2]) * CCH;
            }
    }
    __syncthreads();

    const int lane = tid & 31;
    const int warp = tid >> 5;
    const __half* base = g_xt + (size_t)gb * BVOL + 2 * lane;

    #pragma unroll
    for (int qq = 0; qq < 4; qq += 2) {
        const int q0 = warp * 4 + qq;
        const int q1 = q0 + 1;

        const int4 oA0 = *(const int4*)&s_off[q0][0];
        const int4 oB0 = *(const int4*)&s_off[q0][4];
        const int  o80 = s_off[q0][8];
        const int4 oA1 = *(const int4*)&s_off[q1][0];
        const int4 oB1 = *(const int4*)&s_off[q1][4];
        const int  o81 = s_off[q1][8];
        const int off0[9] = {oA0.x, oA0.y, oA0.z, oA0.w, oB0.x, oB0.y, oB0.z, oB0.w, o80};
        const int off1[9] = {oA1.x, oA1.y, oA1.z, oA1.w, oB1.x, oB1.y, oB1.z, oB1.w, o81};

        const float4 wA0 = *(const float4*)&s_w[q0][0];
        const float4 wB0 = *(const float4*)&s_w[q0][4];
        const float  w80 = s_w[q0][8];
        const float4 wA1 = *(const float4*)&s_w[q1][0];
        const float4 wB1 = *(const float4*)&s_w[q1][4];
        const float  w81 = s_w[q1][8];
        const float w0[9] = {wA0.x, wA0.y, wA0.z, wA0.w, wB0.x, wB0.y, wB0.z, wB0.w, w80};
        const float w1[9] = {wA1.x, wA1.y, wA1.z, wA1.w, wB1.x, wB1.y, wB1.z, wB1.w, w81};

        unsigned v0[9], v1[9];
        #pragma unroll
        for (int k = 0; k < 9; k++)
            v0[k] = *(const unsigned*)(base + off0[k]);
        #pragma unroll
        for (int k = 0; k < 9; k++)
            v1[k] = *(const unsigned*)(base + off1[k]);

        float2 a0 = make_float2(0.f, 0.f);
        float2 a1 = make_float2(0.f, 0.f);
        #pragma unroll
        for (int k = 0; k < 9; k++) {
            const float2 f0 = __half22float2(*(const __half2*)&v0[k]);
            const float2 f1 = __half22float2(*(const __half2*)&v1[k]);
            a0.x += w0[k] * f0.x;  a0.y += w0[k] * f0.y;
            a1.x += w1[k] * f1.x;  a1.y += w1[k] * f1.y;
        }
        s_out[lane][q0] = a0;
        s_out[lane][q1] = a1;
    }
    __syncthreads();

    float* ob = out + (size_t)gb * CCH * NPTS + n0;
    #pragma unroll
    for (int i = tid; i < CCH * 32; i += 256) {
        const int j = i & 31;
        const int c = i >> 5;
        const float2 v = s_out[c >> 1][j];
        __stcs(ob + (size_t)c * NPTS + j, (c & 1) ? v.y : v.x);
    }
}

// ---------------------------------------------------------------------------
// One launch, software-pipelined by bid order:
//   [T0 x4096][T1||G0 x5120][T2||G1][T3||G2][G3 x1024]
// G waits target strictly earlier bids -> deadlock-free.
// ---------------------------------------------------------------------------
__global__ __launch_bounds__(256, 6) void fused_kernel(
    const float* __restrict__ x,
    const float* __restrict__ coords,
    float*       __restrict__ out)
{
    __shared__ __align__(16) char smem[64 * 65 * 4];   // 16640 B, role-unioned

    const int bid = blockIdx.x;
    if (bid < NTB) {
        do_transpose(smem, x, 0, bid);
    } else if (bid >= NTB + 3 * (NTB + NGB)) {
        do_gather(smem, coords, out, NB - 1, bid - (NTB + 3 * (NTB + NGB)));
    } else {
        const int i = bid - NTB;
        const int k = i / (NTB + NGB) + 1;     // transpose batch 1..3
        const int j = i % (NTB + NGB);
        const int g = j / 5;
        const int r = j % 5;
        if (r == 4) do_gather(smem, coords, out, k - 1, g);
        else        do_transpose(smem, x, k, g * 4 + r);
    }
}

extern "C" void kernel_launch(void* const* d_in, const int* in_sizes, int n_in,
                              void* d_out, int out_size) {
    const float* x      = (const float*)d_in[0];
    const float* coords = (const float*)d_in[1];
    if (n_in >= 2 && in_sizes[0] == NB * NPTS * 2) {   // defensive swap
        const float* t = x; x = coords; coords = t;
    }
    float* out = (float*)d_out;

    init_kernel<<<1, 32>>>();
    fused_kernel<<<NB * (NTB + NGB), 256>>>(x, coords, out);
}

// round 10
// speedup vs baseline: 1.3304x; 1.3304x over previous
#include <cuda_runtime.h>
#include <cuda_fp16.h>

#define NX    512
#define NPTS  32768
#define CCH   64
#define NB    4
#define PLANE (NX * NX)
#define BVOL  (PLANE * CCH)

// NHWC fp16 scratch (b, py, px, c). 134 MB.
__device__ __half g_xt[(size_t)NB * BVOL];

// ---------------------------------------------------------------------------
// Kernel 1: NCHW fp32 -> NHWC fp16. Tile = 64 px x 64 ch, 256 threads.
// Loads: 4x LDG.128 per thread. Pack: 2x STG.128 per thread (int4 of 8 ch).
// ---------------------------------------------------------------------------
__global__ __launch_bounds__(256) void transpose_kernel(const float* __restrict__ x)
{
    __shared__ float s[64][65];               // [channel][pixel]

    const int tile = blockIdx.x;
    const int b    = tile >> 12;              // 4096 tiles per batch
    const int p0   = (tile & 4095) * 64;

    const int slot = threadIdx.x & 15;        // float4 slot (4 px)
    const int c0   = threadIdx.x >> 4;        // 0..15

    const float* xb = x + (size_t)b * BVOL;
    #pragma unroll
    for (int c = c0; c < 64; c += 16) {
        const float4 v = __ldcs((const float4*)(xb + (size_t)c * PLANE + p0 + slot * 4));
        s[c][slot * 4 + 0] = v.x;
        s[c][slot * 4 + 1] = v.y;
        s[c][slot * 4 + 2] = v.z;
        s[c][slot * 4 + 3] = v.w;
    }
    __syncthreads();

    __half* yb = g_xt + (size_t)b * BVOL + (size_t)p0 * CCH;
    #pragma unroll
    for (int i = threadIdx.x; i < 64 * 8; i += 256) {
        const int p   = i >> 3;               // pixel
        const int oct = i & 7;                // 8-channel octet
        __half2 h[4];
        #pragma unroll
        for (int j = 0; j < 4; j++)
            h[j] = __floats2half2_rn(s[oct * 8 + 2 * j][p], s[oct * 8 + 2 * j + 1][p]);
        *(int4*)(yb + (size_t)p * CCH + oct * 8) = *(const int4*)h;   // STG.128
    }
}

// ---------------------------------------------------------------------------
// Kernel 2: gather. Block = 256 threads, 32 consecutive points.
// Phase 2: lane = channel quad (4 ch via LDG.64), half-warp per point,
// 2 iterations x 2 points per warp. 9 LDG.64 + 6 LDS.128 per 2 points.
// ---------------------------------------------------------------------------
__global__ __launch_bounds__(256) void gather_kernel(
    const float* __restrict__ coords,
    float*       __restrict__ out)
{
    __shared__ __align__(16) float s_w[32][12];    // 9 used, 48B rows
    __shared__ __align__(16) int   s_off[32][12];  // half-elem offsets in batch
    __shared__ float s_out[64][33];                // [channel][point]

    const int p0g = blockIdx.x * 32;
    const int b   = p0g / NPTS;
    const int n0  = p0g % NPTS;
    const int tid = threadIdx.x;

    // ---- Phase 1: per-point normalized 3x3 weights + offsets ----
    if (tid < 32) {
        const int   n    = n0 + tid;
        const float cy   = coords[((size_t)b * NPTS + n) * 2 + 0];
        const float cx   = coords[((size_t)b * NPTS + n) * 2 + 1];
        const float posx = cx * 511.0f;
        const float posy = cy * 511.0f;
        const float rx   = rintf(posx);       // jnp.round = half-to-even
        const float ry   = rintf(posy);

        float wx[3] = {0.f, 0.f, 0.f};
        float wy[3] = {0.f, 0.f, 0.f};
        #pragma unroll
        for (int j = 0; j < 9; j++) {
            const float o  = 1.5f - 0.375f * (float)j;           // off_n[j]
            const float px = fminf(fmaxf(rx - o, 0.f), 512.f);   // clip hi = nx (ref quirk)
            const float py = fminf(fmaxf(ry - o, 0.f), 512.f);
            const float dx = px - posx;
            const float dy = py - posy;
            wx[j / 3] += __expf(-2.f * dx * dx);  // normal const cancels in norm
            wy[j / 3] += __expf(-2.f * dy * dy);
        }

        float w9[9];
        float s = 0.f;
        #pragma unroll
        for (int a = 0; a < 3; a++)
            #pragma unroll
            for (int c2 = 0; c2 < 3; c2++) {
                const float w = wx[a] * wy[c2];
                w9[a * 3 + c2] = w;
                s += w;
            }
        const float inv = 1.0f / s;

        const int irx = (int)rx;
        const int iry = (int)ry;
        int ixs[3], iys[3];
        #pragma unroll
        for (int a = 0; a < 3; a++) {
            ixs[a] = min(max(irx + 1 - a, 0), NX - 1);
            iys[a] = min(max(iry + 1 - a, 0), NX - 1);
        }

        #pragma unroll
        for (int a = 0; a < 3; a++)
            #pragma unroll
            for (int c2 = 0; c2 < 3; c2++) {
                s_w[tid][a * 3 + c2]   = w9[a * 3 + c2] * inv;
                s_off[tid][a * 3 + c2] = (ixs[a] * NX + iys[c2]) * CCH;
            }
    }
    __syncthreads();

    // ---- Phase 2: dense fp16 NHWC gather, LDG.64 per tap ----
    const int lane = tid & 31;
    const int warp = tid >> 5;
    const int cq   = lane & 15;               // channel quad (4 ch)
    const int sub  = lane >> 4;               // half-warp -> point select
    const __half* bp = g_xt + (size_t)b * BVOL + 4 * cq;

    #pragma unroll
    for (int it = 0; it < 2; it++) {
        const int p = warp * 4 + it * 2 + sub;

        const int4 oA = *(const int4*)&s_off[p][0];
        const int4 oB = *(const int4*)&s_off[p][4];
        const int  o8 = s_off[p][8];
        const int off[9] = {oA.x, oA.y, oA.z, oA.w, oB.x, oB.y, oB.z, oB.w, o8};

        const float4 wA = *(const float4*)&s_w[p][0];
        const float4 wB = *(const float4*)&s_w[p][4];
        const float  w8 = s_w[p][8];
        const float w[9] = {wA.x, wA.y, wA.z, wA.w, wB.x, wB.y, wB.z, wB.w, w8};

        int2 v[9];
        #pragma unroll
        for (int k = 0; k < 9; k++)
            v[k] = *(const int2*)(bp + off[k]);      // LDG.64, 4 channels

        float ax = 0.f, ay = 0.f, az = 0.f, aw = 0.f;
        #pragma unroll
        for (int k = 0; k < 9; k++) {
            const float2 f0 = __half22float2(*(const __half2*)&v[k].x);
            const float2 f1 = __half22float2(*(const __half2*)&v[k].y);
            ax += w[k] * f0.x;  ay += w[k] * f0.y;
            az += w[k] * f1.x;  aw += w[k] * f1.y;
        }
        s_out[4 * cq + 0][p] = ax;
        s_out[4 * cq + 1][p] = ay;
        s_out[4 * cq + 2][p] = az;
        s_out[4 * cq + 3][p] = aw;
    }
    __syncthreads();

    // ---- Phase 3: coalesced (c, n) writes, conflict-free smem reads ----
    float* ob = out + (size_t)b * CCH * NPTS + n0;
    #pragma unroll
    for (int i = tid; i < CCH * 32; i += 256) {
        const int j = i & 31;
        const int c = i >> 5;
        __stcs(ob + (size_t)c * NPTS + j, s_out[c][j]);
    }
}

extern "C" void kernel_launch(void* const* d_in, const int* in_sizes, int n_in,
                              void* d_out, int out_size) {
    const float* x      = (const float*)d_in[0];
    const float* coords = (const float*)d_in[1];
    if (n_in >= 2 && in_sizes[0] == NB * NPTS * 2) {   // defensive swap
        const float* t = x; x = coords; coords = t;
    }
    float* out = (float*)d_out;

    transpose_kernel<<<NB * (PLANE / 64), 256>>>(x);
    gather_kernel<<<(NB * NPTS) / 32, 256>>>(coords, out);
}